// round 12
// baseline (speedup 1.0000x reference)
#include <cuda_runtime.h>
#include <cuda_bf16.h>
#include <cuda_fp16.h>
#include <cstdint>

// Problem constants (fixed shapes per setup_inputs)
#define B_  4
#define N_  20000
#define DN_ 64
#define DM_ 128
#define E_  160000
#define L_  2
#define BN3 384   // 3 * DM

// ---------------- device scratch (no allocations allowed) ----------------
__device__ __half g_HW[(size_t)B_ * N_ * BN3];  // per-relation transformed nodes (fp16)
__device__ float g_eagg[(size_t)N_ * DM_];      // per-node edge-term aggregate (batch independent)
__device__ float g_S[2 * N_ * 16];              // per-node sum of edge attrs per relation
__device__ int   g_deg[3 * N_];
__device__ int   g_off[3 * N_];
__device__ int   g_cur[3 * N_];
__device__ int   g_csr[3 * E_];                 // src node ids grouped by dst
__device__ int   g_csre[3 * E_];                // edge ids grouped by dst
// pre-split, pre-transposed weights: [mat 0..6][hi/mid][n 0..127][k 0..127] bf16
__device__ __nv_bfloat16 g_Wsplit[(size_t)7 * 2 * 128 * 128];
// pre-split activations (A operand), [row 0..79999][k 0..127]
__device__ __nv_bfloat16 g_Ahi[(size_t)B_ * N_ * 128];
__device__ __nv_bfloat16 g_Amid[(size_t)B_ * N_ * 128];

// ==================== CSR build ====================
__global__ void k_zero() {
    int i = blockIdx.x * blockDim.x + threadIdx.x;
    if (i < 3 * N_) g_deg[i] = 0;
}

__global__ void k_count(const int* __restrict__ e0, const int* __restrict__ e1,
                        const int* __restrict__ e2) {
    int t = blockIdx.x * blockDim.x + threadIdx.x;
    if (t >= 3 * E_) return;
    int r = t / E_, e = t - r * E_;
    const int* ei = (r == 0) ? e0 : (r == 1) ? e1 : e2;
    int dst = ei[E_ + e];
    atomicAdd(&g_deg[r * N_ + dst], 1);
}

__global__ void k_scan() {
    __shared__ int sh[1024];
    int r = blockIdx.x;
    int t = threadIdx.x;
    const int CH = 20;
    int base = t * CH;
    int part = 0;
    for (int i = 0; i < CH; ++i) {
        int idx = base + i;
        if (idx < N_) part += g_deg[r * N_ + idx];
    }
    sh[t] = part;
    __syncthreads();
    for (int o = 1; o < 1024; o <<= 1) {
        int v = (t >= o) ? sh[t - o] : 0;
        __syncthreads();
        sh[t] += v;
        __syncthreads();
    }
    int run = (t > 0) ? sh[t - 1] : 0;
    for (int i = 0; i < CH; ++i) {
        int idx = base + i;
        if (idx < N_) {
            g_off[r * N_ + idx] = run;
            g_cur[r * N_ + idx] = run;
            run += g_deg[r * N_ + idx];
        }
    }
}

__global__ void k_fill(const int* __restrict__ e0, const int* __restrict__ e1,
                       const int* __restrict__ e2) {
    int t = blockIdx.x * blockDim.x + threadIdx.x;
    if (t >= 3 * E_) return;
    int r = t / E_, e = t - r * E_;
    const int* ei = (r == 0) ? e0 : (r == 1) ? e1 : e2;
    int src = ei[e];
    int dst = ei[E_ + e];
    int pos = atomicAdd(&g_cur[r * N_ + dst], 1);
    g_csr[r * E_ + pos] = src;
    g_csre[r * E_ + pos] = e;
}

// S_r[n,k] = sum over in-edges of ea_r[e,k]  (gather, deterministic)
__global__ void k_gatherS(const float* __restrict__ ea0, const float* __restrict__ ea1) {
    int n = blockIdx.x * 8 + (threadIdx.x >> 4);
    int k = threadIdx.x & 15;
    int r = blockIdx.y;
    if (n >= N_) return;
    const float* ea = r ? ea1 : ea0;
    const int* __restrict__ eids = &g_csre[r * E_];
    int beg = g_off[r * N_ + n];
    int end = beg + g_deg[r * N_ + n];
    float s = 0.f;
    for (int i = beg; i < end; ++i)
        s += ea[(size_t)eids[i] * 16 + k];
    g_S[(r * N_ + n) * 16 + k] = s;
}

// ==================== weight pre-split (transpose + bf16 hi/mid) ====================
__global__ void k_prepW(const float* __restrict__ in_W, const float* __restrict__ node_W) {
    int m = blockIdx.x;   // 0..6
    const float* src = (m == 0) ? in_W : node_W + (size_t)(m - 1) * 128 * 128;
    int K = (m == 0) ? 64 : 128;
    __nv_bfloat16* hi = g_Wsplit + (size_t)m * 2 * 128 * 128;
    __nv_bfloat16* mid = hi + 128 * 128;
    for (int i = threadIdx.x; i < K * 128; i += blockDim.x) {
        int k = i >> 7, n = i & 127;
        float x = src[i];
        __nv_bfloat16 h = __float2bfloat16_rn(x);
        __nv_bfloat16 md = __float2bfloat16_rn(x - __bfloat162float(h));
        hi[n * 128 + k] = h;
        mid[n * 128 + k] = md;
    }
}

// ==================== activation pre-split (node_feat only, K=64) ====================
__global__ __launch_bounds__(256) void k_prepA(const float* __restrict__ A, int kshift, int total4) {
    int i = blockIdx.x * blockDim.x + threadIdx.x;
    if (i >= total4) return;
    int c4 = i << 2;
    int r = c4 >> kshift;
    int c = c4 & ((1 << kshift) - 1);
    float4 v = *(const float4*)&A[c4];
    __nv_bfloat162 h01, h23, m01, m23;
    h01.x = __float2bfloat16_rn(v.x);
    h01.y = __float2bfloat16_rn(v.y);
    h23.x = __float2bfloat16_rn(v.z);
    h23.y = __float2bfloat16_rn(v.w);
    m01.x = __float2bfloat16_rn(v.x - __bfloat162float(h01.x));
    m01.y = __float2bfloat16_rn(v.y - __bfloat162float(h01.y));
    m23.x = __float2bfloat16_rn(v.z - __bfloat162float(h23.x));
    m23.y = __float2bfloat16_rn(v.w - __bfloat162float(h23.y));
    size_t o = (size_t)r * 128 + c;
    uint2 hv, mv;
    hv.x = *(uint32_t*)&h01; hv.y = *(uint32_t*)&h23;
    mv.x = *(uint32_t*)&m01; mv.y = *(uint32_t*)&m23;
    *(uint2*)&g_Ahi[o] = hv;
    *(uint2*)&g_Amid[o] = mv;
}

// ==================== HMMA GEMM (cp.async double-buffered, R10 core) ====================
// 256 thr = 8 warps (2M x 4N), warp tile 64x32, BK=32, 2 stages. 80 KB smem -> 2 CTA/SM.
#define SROW 40
#define ARR_ELEMS (128 * SROW)
#define GEMM_SMEM_BYTES (2 * 4 * ARR_ELEMS * 2)   // 81920

__device__ __forceinline__ uint32_t smem_u32(const void* p) {
    uint32_t a;
    asm("{ .reg .u64 t; cvta.to.shared.u64 t, %1; cvt.u32.u64 %0, t; }" : "=r"(a) : "l"(p));
    return a;
}
__device__ __forceinline__ void cp16(uint32_t dst, const void* src) {
    asm volatile("cp.async.ca.shared.global [%0], [%1], 16;" :: "r"(dst), "l"(src));
}
#define CP_COMMIT() asm volatile("cp.async.commit_group;" ::: "memory")

__device__ __forceinline__ void mma16816(float* c, const uint32_t* a, const uint32_t* b) {
    asm volatile(
        "mma.sync.aligned.m16n8k16.row.col.f32.bf16.bf16.f32 "
        "{%0,%1,%2,%3}, {%4,%5,%6,%7}, {%8,%9}, {%0,%1,%2,%3};"
        : "+f"(c[0]), "+f"(c[1]), "+f"(c[2]), "+f"(c[3])
        : "r"(a[0]), "r"(a[1]), "r"(a[2]), "r"(a[3]), "r"(b[0]), "r"(b[1]));
}

__global__ __launch_bounds__(256)
void k_gemm(int matBase, const float* __restrict__ biasBase, int strideBias,
            float* __restrict__ outF32, __half* __restrict__ outF16,
            int ldC, int K, int emitSplit) {
    extern __shared__ __nv_bfloat16 smem[];
    const int tid = threadIdx.x;
    const int wid = tid >> 5;
    const int lane = tid & 31;
    const int g = lane >> 2;
    const int t = lane & 3;
    const int wm = wid & 1;
    const int wn = wid >> 1;
    const int row0 = blockIdx.x * 128;
    const int mat = matBase + blockIdx.y;
    const float* bias = biasBase + (size_t)blockIdx.y * strideBias;
    const int colBase = blockIdx.y * 128;
    const __nv_bfloat16* Whi = g_Wsplit + (size_t)mat * 2 * 128 * 128;
    const __nv_bfloat16* Wmid = Whi + 128 * 128;
    const uint32_t sb = smem_u32(smem);

    float acc[4][4][4];
#pragma unroll
    for (int i = 0; i < 4; ++i)
#pragma unroll
        for (int j = 0; j < 4; ++j)
#pragma unroll
            for (int q = 0; q < 4; ++q) acc[i][j][q] = 0.f;

    const int nStages = K >> 5;

    auto issueStage = [&](int buf, int kc) {
#pragma unroll
        for (int tt = 0; tt < 8; ++tt) {
            int f = tid + tt * 256;
            int arr = f >> 9;
            int gg = f & 511;
            int row = gg >> 2;
            int u = (gg & 3) * 8;
            const __nv_bfloat16* src;
            if (arr == 0)      src = &g_Ahi[(size_t)(row0 + row) * 128 + kc + u];
            else if (arr == 1) src = &g_Amid[(size_t)(row0 + row) * 128 + kc + u];
            else if (arr == 2) src = &Whi[(size_t)row * 128 + kc + u];
            else               src = &Wmid[(size_t)row * 128 + kc + u];
            uint32_t dst = sb + ((buf * 4 + arr) * ARR_ELEMS + row * SROW + u) * 2;
            cp16(dst, src);
        }
        CP_COMMIT();
    };

    issueStage(0, 0);

    for (int st = 0; st < nStages; ++st) {
        const int buf = st & 1;
        if (st + 1 < nStages) {
            issueStage(buf ^ 1, (st + 1) << 5);
            asm volatile("cp.async.wait_group 1;" ::: "memory");
        } else {
            asm volatile("cp.async.wait_group 0;" ::: "memory");
        }
        __syncthreads();

        const __nv_bfloat16* sAhi  = smem + (buf * 4 + 0) * ARR_ELEMS;
        const __nv_bfloat16* sAmid = smem + (buf * 4 + 1) * ARR_ELEMS;
        const __nv_bfloat16* sBhi  = smem + (buf * 4 + 2) * ARR_ELEMS;
        const __nv_bfloat16* sBmid = smem + (buf * 4 + 3) * ARR_ELEMS;

#pragma unroll
        for (int kk = 0; kk < 2; ++kk) {
            const int k0 = kk << 4;
            uint32_t bh[4][2], bm[4][2];
#pragma unroll
            for (int j = 0; j < 4; ++j) {
                int n_idx = wn * 32 + j * 8 + g;
                int o0 = n_idx * SROW + k0 + t * 2;
                bh[j][0] = *(const uint32_t*)&sBhi[o0];
                bh[j][1] = *(const uint32_t*)&sBhi[o0 + 8];
                bm[j][0] = *(const uint32_t*)&sBmid[o0];
                bm[j][1] = *(const uint32_t*)&sBmid[o0 + 8];
            }
#pragma unroll
            for (int i = 0; i < 4; ++i) {
                int m_idx = wm * 64 + i * 16 + g;
                int o0 = m_idx * SROW + k0 + t * 2;
                int o8 = (m_idx + 8) * SROW + k0 + t * 2;
                uint32_t ah[4], am[4];
                ah[0] = *(const uint32_t*)&sAhi[o0];
                ah[1] = *(const uint32_t*)&sAhi[o8];
                ah[2] = *(const uint32_t*)&sAhi[o0 + 8];
                ah[3] = *(const uint32_t*)&sAhi[o8 + 8];
                am[0] = *(const uint32_t*)&sAmid[o0];
                am[1] = *(const uint32_t*)&sAmid[o8];
                am[2] = *(const uint32_t*)&sAmid[o0 + 8];
                am[3] = *(const uint32_t*)&sAmid[o8 + 8];
#pragma unroll
                for (int j = 0; j < 4; ++j) {
                    mma16816(acc[i][j], ah, bh[j]);   // hi*hi
                    mma16816(acc[i][j], ah, bm[j]);   // hi*mid
                    mma16816(acc[i][j], am, bh[j]);   // mid*hi
                }
            }
        }
        __syncthreads();
    }

    // ---- epilogue ----
#pragma unroll
    for (int i = 0; i < 4; ++i) {
#pragma unroll
        for (int j = 0; j < 4; ++j) {
            int col = wn * 32 + j * 8 + t * 2;
            int row = row0 + wm * 64 + i * 16 + g;
            float b0 = bias[col], b1 = bias[col + 1];
            float v00 = acc[i][j][0] + b0, v01 = acc[i][j][1] + b1;
            float v10 = acc[i][j][2] + b0, v11 = acc[i][j][3] + b1;
            if (outF32) {
                *(float2*)&outF32[(size_t)row * ldC + colBase + col] = make_float2(v00, v01);
                *(float2*)&outF32[(size_t)(row + 8) * ldC + colBase + col] = make_float2(v10, v11);
                if (emitSplit) {
                    __nv_bfloat162 h0, m0, h1, m1;
                    h0.x = __float2bfloat16_rn(v00); h0.y = __float2bfloat16_rn(v01);
                    m0.x = __float2bfloat16_rn(v00 - __bfloat162float(h0.x));
                    m0.y = __float2bfloat16_rn(v01 - __bfloat162float(h0.y));
                    h1.x = __float2bfloat16_rn(v10); h1.y = __float2bfloat16_rn(v11);
                    m1.x = __float2bfloat16_rn(v10 - __bfloat162float(h1.x));
                    m1.y = __float2bfloat16_rn(v11 - __bfloat162float(h1.y));
                    *(__nv_bfloat162*)&g_Ahi[(size_t)row * 128 + col] = h0;
                    *(__nv_bfloat162*)&g_Amid[(size_t)row * 128 + col] = m0;
                    *(__nv_bfloat162*)&g_Ahi[(size_t)(row + 8) * 128 + col] = h1;
                    *(__nv_bfloat162*)&g_Amid[(size_t)(row + 8) * 128 + col] = m1;
                }
            } else {
                __half2 h0 = __float22half2_rn(make_float2(v00, v01));
                __half2 h1 = __float22half2_rn(make_float2(v10, v11));
                *(__half2*)&outF16[(size_t)row * ldC + colBase + col] = h0;
                *(__half2*)&outF16[(size_t)(row + 8) * ldC + colBase + col] = h1;
            }
        }
    }
}

// ==================== per-layer edge-term aggregate ====================
__global__ void k_eagg(const float* __restrict__ edge_W, const float* __restrict__ edge_b, int l) {
    int n = blockIdx.x;
    int j = threadIdx.x;   // 128
    __shared__ float s0[16], s1[16];
    if (j < 16) s0[j] = g_S[(0 * N_ + n) * 16 + j];
    else if (j < 32) s1[j - 16] = g_S[(1 * N_ + n) * 16 + (j - 16)];
    __syncthreads();

    const float* W0 = edge_W + (size_t)(l * 2 + 0) * 16 * 128;
    const float* W1 = edge_W + (size_t)(l * 2 + 1) * 16 * 128;
    float d0 = (float)g_deg[0 * N_ + n];
    float d1 = (float)g_deg[1 * N_ + n];
    float acc = d0 * edge_b[(l * 2 + 0) * 128 + j] + d1 * edge_b[(l * 2 + 1) * 128 + j];
#pragma unroll
    for (int k = 0; k < 16; ++k) acc = fmaf(s0[k], W0[k * 128 + j], acc);
#pragma unroll
    for (int k = 0; k < 16; ++k) acc = fmaf(s1[k], W1[k * 128 + j], acc);
    g_eagg[(size_t)n * 128 + j] = acc;
}

// ==================== fused gather-aggregate + relu + residual + LayerNorm ====================
__global__ __launch_bounds__(256) void k_agg_ln(float* __restrict__ H,
                                                const float* __restrict__ gamma,
                                                const float* __restrict__ beta,
                                                int emitSplit) {
    int warp = (blockIdx.x * blockDim.x + threadIdx.x) >> 5;
    int lane = threadIdx.x & 31;
    if (warp >= B_ * N_) return;
    int b = warp / N_;
    int n = warp - b * N_;
    int j4 = lane * 4;

    float4 acc = *(const float4*)&g_eagg[(size_t)n * 128 + j4];
    const size_t hwBatch = (size_t)b * N_ * BN3;

#pragma unroll
    for (int r = 0; r < 3; ++r) {
        int beg = g_off[r * N_ + n];
        int end = beg + g_deg[r * N_ + n];
        const int* __restrict__ srcs = &g_csr[r * E_];
        const int colOff = r * 128 + j4;
        for (int i = beg; i < end; ++i) {
            int s = srcs[i];
            uint2 u = *(const uint2*)&g_HW[hwBatch + (size_t)s * BN3 + colOff];
            float2 f0 = __half22float2(*(__half2*)&u.x);
            float2 f1 = __half22float2(*(__half2*)&u.y);
            acc.x += f0.x; acc.y += f0.y; acc.z += f1.x; acc.w += f1.y;
        }
    }
    acc.x = fmaxf(acc.x, 0.f);
    acc.y = fmaxf(acc.y, 0.f);
    acc.z = fmaxf(acc.z, 0.f);
    acc.w = fmaxf(acc.w, 0.f);

    size_t hIdx = ((size_t)b * N_ + n) * 128 + j4;
    float4 h = *(const float4*)&H[hIdx];
    float x0 = h.x + acc.x, x1 = h.y + acc.y, x2 = h.z + acc.z, x3 = h.w + acc.w;

    float s = x0 + x1 + x2 + x3;
    float s2 = x0 * x0 + x1 * x1 + x2 * x2 + x3 * x3;
#pragma unroll
    for (int o = 16; o > 0; o >>= 1) {
        s += __shfl_xor_sync(0xffffffffu, s, o);
        s2 += __shfl_xor_sync(0xffffffffu, s2, o);
    }
    float mu = s * (1.f / 128.f);
    float var = s2 * (1.f / 128.f) - mu * mu;
    float inv = rsqrtf(var + 1e-5f);

    float4 gm = *(const float4*)&gamma[j4];
    float4 bb = *(const float4*)&beta[j4];
    float4 out;
    out.x = (x0 - mu) * inv * gm.x + bb.x;
    out.y = (x1 - mu) * inv * gm.y + bb.y;
    out.z = (x2 - mu) * inv * gm.z + bb.z;
    out.w = (x3 - mu) * inv * gm.w + bb.w;
    *(float4*)&H[hIdx] = out;

    if (emitSplit) {
        __nv_bfloat162 h01, h23, m01, m23;
        h01.x = __float2bfloat16_rn(out.x);
        h01.y = __float2bfloat16_rn(out.y);
        h23.x = __float2bfloat16_rn(out.z);
        h23.y = __float2bfloat16_rn(out.w);
        m01.x = __float2bfloat16_rn(out.x - __bfloat162float(h01.x));
        m01.y = __float2bfloat16_rn(out.y - __bfloat162float(h01.y));
        m23.x = __float2bfloat16_rn(out.z - __bfloat162float(h23.x));
        m23.y = __float2bfloat16_rn(out.w - __bfloat162float(h23.y));
        uint2 hv, mv;
        hv.x = *(uint32_t*)&h01; hv.y = *(uint32_t*)&h23;
        mv.x = *(uint32_t*)&m01; mv.y = *(uint32_t*)&m23;
        *(uint2*)&g_Ahi[hIdx] = hv;
        *(uint2*)&g_Amid[hIdx] = mv;
    }
}

// ==================== launch ====================
extern "C" void kernel_launch(void* const* d_in, const int* in_sizes, int n_in,
                              void* d_out, int out_size) {
    const float* node_feat = (const float*)d_in[0];
    const float* in_W      = (const float*)d_in[1];
    const float* in_b      = (const float*)d_in[2];
    const float* node_W    = (const float*)d_in[3];
    const float* node_b    = (const float*)d_in[4];
    const float* edge_W    = (const float*)d_in[5];
    const float* edge_b    = (const float*)d_in[6];
    const float* ln_g      = (const float*)d_in[7];
    const float* ln_b      = (const float*)d_in[8];
    const float* ea0       = (const float*)d_in[9];
    const float* ea1       = (const float*)d_in[10];
    const int*   e0        = (const int*)d_in[11];
    const int*   e1        = (const int*)d_in[12];
    const int*   e2        = (const int*)d_in[13];
    float* H = (float*)d_out;

    __half* hw16 = nullptr;
    cudaGetSymbolAddress((void**)&hw16, g_HW);

    cudaFuncSetAttribute(k_gemm, cudaFuncAttributeMaxDynamicSharedMemorySize,
                         GEMM_SMEM_BYTES);

    // index structures + weight pre-split
    k_zero<<<(3 * N_ + 255) / 256, 256>>>();
    k_count<<<(3 * E_ + 255) / 256, 256>>>(e0, e1, e2);
    k_scan<<<3, 1024>>>();
    k_fill<<<(3 * E_ + 255) / 256, 256>>>(e0, e1, e2);
    k_gatherS<<<dim3((N_ + 7) / 8, 2), 128>>>(ea0, ea1);
    k_prepW<<<7, 256>>>(in_W, node_W);

    // input projection: H = node_feat @ in_W + in_b; epilogue emits bf16 split of H
    k_prepA<<<(B_ * N_ * DN_ / 4 + 255) / 256, 256>>>(node_feat, 6, B_ * N_ * DN_ / 4);
    k_gemm<<<dim3(625, 1), 256, GEMM_SMEM_BYTES>>>(0, in_b, 0, H, nullptr, DM_, DN_, 1);

    for (int l = 0; l < L_; ++l) {
        // g_HW[:, r] = H @ node_W[l,r] + node_b[l,r]  (fp16 out)
        k_gemm<<<dim3(625, 3), 256, GEMM_SMEM_BYTES>>>(
            1 + l * 3, node_b + (size_t)l * 3 * DM_, DM_, nullptr, hw16, BN3, DM_, 0);
        k_eagg<<<N_, 128>>>(edge_W, edge_b, l);
        k_agg_ln<<<(B_ * N_ * 32 + 255) / 256, 256>>>(H, ln_g + l * DM_, ln_b + l * DM_,
                                                      (l == 0) ? 1 : 0);
    }
}

// round 13
// speedup vs baseline: 1.5995x; 1.5995x over previous
#include <cuda_runtime.h>
#include <cuda_bf16.h>
#include <cuda_fp16.h>
#include <cstdint>

// Problem constants (fixed shapes per setup_inputs)
#define B_  4
#define N_  20000
#define DN_ 64
#define DM_ 128
#define E_  160000
#define L_  2
#define BN3 384   // 3 * DM

// ---------------- device scratch (no allocations allowed) ----------------
__device__ __half g_HW[(size_t)B_ * N_ * BN3];  // per-relation transformed nodes (fp16)
__device__ float g_eagg[(size_t)L_ * N_ * DM_]; // per-node edge-term aggregate, both layers
__device__ float g_S[2 * N_ * 16];              // per-node sum of edge attrs per relation
__device__ int   g_deg[3 * N_];
__device__ int   g_off[3 * N_];
__device__ int   g_cur[3 * N_];
__device__ int   g_csr[3 * E_];                 // src node ids grouped by dst
__device__ int   g_csre[3 * E_];                // edge ids grouped by dst
// pre-split, pre-transposed weights: [mat 0..6][hi/mid][n 0..127][k 0..127] bf16
__device__ __nv_bfloat16 g_Wsplit[(size_t)7 * 2 * 128 * 128];
// pre-split activations (A operand), [row 0..79999][k 0..127]
__device__ __nv_bfloat16 g_Ahi[(size_t)B_ * N_ * 128];
__device__ __nv_bfloat16 g_Amid[(size_t)B_ * N_ * 128];

// ==================== CSR build ====================
__global__ void k_zero() {
    int i = blockIdx.x * blockDim.x + threadIdx.x;
    if (i < 3 * N_) g_deg[i] = 0;
}

__global__ void k_count(const int* __restrict__ e0, const int* __restrict__ e1,
                        const int* __restrict__ e2) {
    int t = blockIdx.x * blockDim.x + threadIdx.x;
    if (t >= 3 * E_) return;
    int r = t / E_, e = t - r * E_;
    const int* ei = (r == 0) ? e0 : (r == 1) ? e1 : e2;
    int dst = ei[E_ + e];
    atomicAdd(&g_deg[r * N_ + dst], 1);
}

__global__ void k_scan() {
    __shared__ int sh[1024];
    int r = blockIdx.x;
    int t = threadIdx.x;
    const int CH = 20;
    int base = t * CH;
    int part = 0;
    for (int i = 0; i < CH; ++i) {
        int idx = base + i;
        if (idx < N_) part += g_deg[r * N_ + idx];
    }
    sh[t] = part;
    __syncthreads();
    for (int o = 1; o < 1024; o <<= 1) {
        int v = (t >= o) ? sh[t - o] : 0;
        __syncthreads();
        sh[t] += v;
        __syncthreads();
    }
    int run = (t > 0) ? sh[t - 1] : 0;
    for (int i = 0; i < CH; ++i) {
        int idx = base + i;
        if (idx < N_) {
            g_off[r * N_ + idx] = run;
            g_cur[r * N_ + idx] = run;
            run += g_deg[r * N_ + idx];
        }
    }
}

__global__ void k_fill(const int* __restrict__ e0, const int* __restrict__ e1,
                       const int* __restrict__ e2) {
    int t = blockIdx.x * blockDim.x + threadIdx.x;
    if (t >= 3 * E_) return;
    int r = t / E_, e = t - r * E_;
    const int* ei = (r == 0) ? e0 : (r == 1) ? e1 : e2;
    int src = ei[e];
    int dst = ei[E_ + e];
    int pos = atomicAdd(&g_cur[r * N_ + dst], 1);
    g_csr[r * E_ + pos] = src;
    g_csre[r * E_ + pos] = e;
}

// S_r[n,k] = sum over in-edges of ea_r[e,k]  (gather, deterministic)
__global__ void k_gatherS(const float* __restrict__ ea0, const float* __restrict__ ea1) {
    int n = blockIdx.x * 8 + (threadIdx.x >> 4);
    int k = threadIdx.x & 15;
    int r = blockIdx.y;
    if (n >= N_) return;
    const float* ea = r ? ea1 : ea0;
    const int* __restrict__ eids = &g_csre[r * E_];
    int beg = g_off[r * N_ + n];
    int end = beg + g_deg[r * N_ + n];
    float s = 0.f;
    for (int i = beg; i < end; ++i)
        s += ea[(size_t)eids[i] * 16 + k];
    g_S[(r * N_ + n) * 16 + k] = s;
}

// ==================== weight pre-split (transpose + bf16 hi/mid) ====================
__global__ void k_prepW(const float* __restrict__ in_W, const float* __restrict__ node_W) {
    int m = blockIdx.x;   // 0..6
    const float* src = (m == 0) ? in_W : node_W + (size_t)(m - 1) * 128 * 128;
    int K = (m == 0) ? 64 : 128;
    __nv_bfloat16* hi = g_Wsplit + (size_t)m * 2 * 128 * 128;
    __nv_bfloat16* mid = hi + 128 * 128;
    for (int i = threadIdx.x; i < K * 128; i += blockDim.x) {
        int k = i >> 7, n = i & 127;
        float x = src[i];
        __nv_bfloat16 h = __float2bfloat16_rn(x);
        __nv_bfloat16 md = __float2bfloat16_rn(x - __bfloat162float(h));
        hi[n * 128 + k] = h;
        mid[n * 128 + k] = md;
    }
}

// ==================== activation pre-split (node_feat only, K=64) ====================
__global__ __launch_bounds__(256) void k_prepA(const float* __restrict__ A, int kshift, int total4) {
    int i = blockIdx.x * blockDim.x + threadIdx.x;
    if (i >= total4) return;
    int c4 = i << 2;
    int r = c4 >> kshift;
    int c = c4 & ((1 << kshift) - 1);
    float4 v = *(const float4*)&A[c4];
    __nv_bfloat162 h01, h23, m01, m23;
    h01.x = __float2bfloat16_rn(v.x);
    h01.y = __float2bfloat16_rn(v.y);
    h23.x = __float2bfloat16_rn(v.z);
    h23.y = __float2bfloat16_rn(v.w);
    m01.x = __float2bfloat16_rn(v.x - __bfloat162float(h01.x));
    m01.y = __float2bfloat16_rn(v.y - __bfloat162float(h01.y));
    m23.x = __float2bfloat16_rn(v.z - __bfloat162float(h23.x));
    m23.y = __float2bfloat16_rn(v.w - __bfloat162float(h23.y));
    size_t o = (size_t)r * 128 + c;
    uint2 hv, mv;
    hv.x = *(uint32_t*)&h01; hv.y = *(uint32_t*)&h23;
    mv.x = *(uint32_t*)&m01; mv.y = *(uint32_t*)&m23;
    *(uint2*)&g_Ahi[o] = hv;
    *(uint2*)&g_Amid[o] = mv;
}

// ==================== HMMA GEMM (cp.async double-buffered, specialized) ====================
// 256 thr = 8 warps (2M x 4N), warp tile 64x32, BK=32, 2 stages. 80 KB smem.
// __launch_bounds__(256, 2) forces regs<=128 -> guaranteed 2 CTA/SM.
#define SROW 40
#define ARR_ELEMS (128 * SROW)
#define GEMM_SMEM_BYTES (2 * 4 * ARR_ELEMS * 2)   // 81920

__device__ __forceinline__ uint32_t smem_u32(const void* p) {
    uint32_t a;
    asm("{ .reg .u64 t; cvta.to.shared.u64 t, %1; cvt.u32.u64 %0, t; }" : "=r"(a) : "l"(p));
    return a;
}
__device__ __forceinline__ void cp16(uint32_t dst, const void* src) {
    asm volatile("cp.async.ca.shared.global [%0], [%1], 16;" :: "r"(dst), "l"(src));
}
#define CP_COMMIT() asm volatile("cp.async.commit_group;" ::: "memory")

__device__ __forceinline__ void mma16816(float* c, const uint32_t* a, const uint32_t* b) {
    asm volatile(
        "mma.sync.aligned.m16n8k16.row.col.f32.bf16.bf16.f32 "
        "{%0,%1,%2,%3}, {%4,%5,%6,%7}, {%8,%9}, {%0,%1,%2,%3};"
        : "+f"(c[0]), "+f"(c[1]), "+f"(c[2]), "+f"(c[3])
        : "r"(a[0]), "r"(a[1]), "r"(a[2]), "r"(a[3]), "r"(b[0]), "r"(b[1]));
}

template<int NSTAGES, bool OUT16, bool EMIT>
__global__ __launch_bounds__(256, 2)
void k_gemm_t(int matBase, const float* __restrict__ biasBase, int strideBias,
              float* __restrict__ outF32, __half* __restrict__ outF16, int ldC) {
    extern __shared__ __nv_bfloat16 smem[];
    const int tid = threadIdx.x;
    const int wid = tid >> 5;
    const int lane = tid & 31;
    const int g = lane >> 2;
    const int t = lane & 3;
    const int wm = wid & 1;
    const int wn = wid >> 1;
    const int row0 = blockIdx.x * 128;
    const int mat = matBase + blockIdx.y;
    const float* bias = biasBase + (size_t)blockIdx.y * strideBias;
    const int colBase = blockIdx.y * 128;
    const __nv_bfloat16* Whi = g_Wsplit + (size_t)mat * 2 * 128 * 128;
    const __nv_bfloat16* Wmid = Whi + 128 * 128;
    const uint32_t sb = smem_u32(smem);

    float acc[4][4][4];
#pragma unroll
    for (int i = 0; i < 4; ++i)
#pragma unroll
        for (int j = 0; j < 4; ++j)
#pragma unroll
            for (int q = 0; q < 4; ++q) acc[i][j][q] = 0.f;

    auto issueStage = [&](int buf, int kc) {
#pragma unroll
        for (int tt = 0; tt < 8; ++tt) {
            int f = tid + tt * 256;
            int arr = f >> 9;
            int gg = f & 511;
            int row = gg >> 2;
            int u = (gg & 3) * 8;
            const __nv_bfloat16* src;
            if (arr == 0)      src = &g_Ahi[(size_t)(row0 + row) * 128 + kc + u];
            else if (arr == 1) src = &g_Amid[(size_t)(row0 + row) * 128 + kc + u];
            else if (arr == 2) src = &Whi[(size_t)row * 128 + kc + u];
            else               src = &Wmid[(size_t)row * 128 + kc + u];
            uint32_t dst = sb + ((buf * 4 + arr) * ARR_ELEMS + row * SROW + u) * 2;
            cp16(dst, src);
        }
        CP_COMMIT();
    };

    issueStage(0, 0);

#pragma unroll
    for (int st = 0; st < NSTAGES; ++st) {
        const int buf = st & 1;
        if (st + 1 < NSTAGES) {
            issueStage(buf ^ 1, (st + 1) << 5);
            asm volatile("cp.async.wait_group 1;" ::: "memory");
        } else {
            asm volatile("cp.async.wait_group 0;" ::: "memory");
        }
        __syncthreads();

        const __nv_bfloat16* sAhi  = smem + (buf * 4 + 0) * ARR_ELEMS;
        const __nv_bfloat16* sAmid = smem + (buf * 4 + 1) * ARR_ELEMS;
        const __nv_bfloat16* sBhi  = smem + (buf * 4 + 2) * ARR_ELEMS;
        const __nv_bfloat16* sBmid = smem + (buf * 4 + 3) * ARR_ELEMS;

#pragma unroll
        for (int kk = 0; kk < 2; ++kk) {
            const int k0 = kk << 4;
            uint32_t bh[4][2], bm[4][2];
#pragma unroll
            for (int j = 0; j < 4; ++j) {
                int n_idx = wn * 32 + j * 8 + g;
                int o0 = n_idx * SROW + k0 + t * 2;
                bh[j][0] = *(const uint32_t*)&sBhi[o0];
                bh[j][1] = *(const uint32_t*)&sBhi[o0 + 8];
                bm[j][0] = *(const uint32_t*)&sBmid[o0];
                bm[j][1] = *(const uint32_t*)&sBmid[o0 + 8];
            }
#pragma unroll
            for (int i = 0; i < 4; ++i) {
                int m_idx = wm * 64 + i * 16 + g;
                int o0 = m_idx * SROW + k0 + t * 2;
                int o8 = (m_idx + 8) * SROW + k0 + t * 2;
                uint32_t ah[4], am[4];
                ah[0] = *(const uint32_t*)&sAhi[o0];
                ah[1] = *(const uint32_t*)&sAhi[o8];
                ah[2] = *(const uint32_t*)&sAhi[o0 + 8];
                ah[3] = *(const uint32_t*)&sAhi[o8 + 8];
                am[0] = *(const uint32_t*)&sAmid[o0];
                am[1] = *(const uint32_t*)&sAmid[o8];
                am[2] = *(const uint32_t*)&sAmid[o0 + 8];
                am[3] = *(const uint32_t*)&sAmid[o8 + 8];
#pragma unroll
                for (int j = 0; j < 4; ++j) {
                    mma16816(acc[i][j], ah, bh[j]);   // hi*hi
                    mma16816(acc[i][j], ah, bm[j]);   // hi*mid
                    mma16816(acc[i][j], am, bh[j]);   // mid*hi
                }
            }
        }
        __syncthreads();
    }

    // ---- epilogue (compile-time specialized) ----
#pragma unroll
    for (int i = 0; i < 4; ++i) {
#pragma unroll
        for (int j = 0; j < 4; ++j) {
            int col = wn * 32 + j * 8 + t * 2;
            int row = row0 + wm * 64 + i * 16 + g;
            float b0 = bias[col], b1 = bias[col + 1];
            float v00 = acc[i][j][0] + b0, v01 = acc[i][j][1] + b1;
            float v10 = acc[i][j][2] + b0, v11 = acc[i][j][3] + b1;
            if (!OUT16) {
                *(float2*)&outF32[(size_t)row * ldC + colBase + col] = make_float2(v00, v01);
                *(float2*)&outF32[(size_t)(row + 8) * ldC + colBase + col] = make_float2(v10, v11);
            } else {
                __half2 h0 = __float22half2_rn(make_float2(v00, v01));
                __half2 h1 = __float22half2_rn(make_float2(v10, v11));
                *(__half2*)&outF16[(size_t)row * ldC + colBase + col] = h0;
                *(__half2*)&outF16[(size_t)(row + 8) * ldC + colBase + col] = h1;
            }
            if (EMIT) {
                __nv_bfloat162 h0, m0, h1, m1;
                h0.x = __float2bfloat16_rn(v00); h0.y = __float2bfloat16_rn(v01);
                m0.x = __float2bfloat16_rn(v00 - __bfloat162float(h0.x));
                m0.y = __float2bfloat16_rn(v01 - __bfloat162float(h0.y));
                h1.x = __float2bfloat16_rn(v10); h1.y = __float2bfloat16_rn(v11);
                m1.x = __float2bfloat16_rn(v10 - __bfloat162float(h1.x));
                m1.y = __float2bfloat16_rn(v11 - __bfloat162float(h1.y));
                *(__nv_bfloat162*)&g_Ahi[(size_t)row * 128 + colBase + col] = h0;
                *(__nv_bfloat162*)&g_Amid[(size_t)row * 128 + colBase + col] = m0;
                *(__nv_bfloat162*)&g_Ahi[(size_t)(row + 8) * 128 + colBase + col] = h1;
                *(__nv_bfloat162*)&g_Amid[(size_t)(row + 8) * 128 + colBase + col] = m1;
            }
        }
    }
}

// ==================== edge-term aggregate, both layers precomputed ====================
__global__ void k_eagg(const float* __restrict__ edge_W, const float* __restrict__ edge_b) {
    int n = blockIdx.x;
    int l = blockIdx.y;
    int j = threadIdx.x;   // 128
    __shared__ float s0[16], s1[16];
    if (j < 16) s0[j] = g_S[(0 * N_ + n) * 16 + j];
    else if (j < 32) s1[j - 16] = g_S[(1 * N_ + n) * 16 + (j - 16)];
    __syncthreads();

    const float* W0 = edge_W + (size_t)(l * 2 + 0) * 16 * 128;
    const float* W1 = edge_W + (size_t)(l * 2 + 1) * 16 * 128;
    float d0 = (float)g_deg[0 * N_ + n];
    float d1 = (float)g_deg[1 * N_ + n];
    float acc = d0 * edge_b[(l * 2 + 0) * 128 + j] + d1 * edge_b[(l * 2 + 1) * 128 + j];
#pragma unroll
    for (int k = 0; k < 16; ++k) acc = fmaf(s0[k], W0[k * 128 + j], acc);
#pragma unroll
    for (int k = 0; k < 16; ++k) acc = fmaf(s1[k], W1[k * 128 + j], acc);
    g_eagg[((size_t)l * N_ + n) * 128 + j] = acc;
}

// ==================== fused gather-aggregate + relu + residual + LayerNorm ====================
__global__ __launch_bounds__(256) void k_agg_ln(float* __restrict__ H,
                                                const float* __restrict__ gamma,
                                                const float* __restrict__ beta,
                                                int l, int emitSplit) {
    int warp = (blockIdx.x * blockDim.x + threadIdx.x) >> 5;
    int lane = threadIdx.x & 31;
    if (warp >= B_ * N_) return;
    int b = warp / N_;
    int n = warp - b * N_;
    int j4 = lane * 4;

    float4 acc = *(const float4*)&g_eagg[((size_t)l * N_ + n) * 128 + j4];
    const size_t hwBatch = (size_t)b * N_ * BN3;

#pragma unroll
    for (int r = 0; r < 3; ++r) {
        int beg = g_off[r * N_ + n];
        int end = beg + g_deg[r * N_ + n];
        const int* __restrict__ srcs = &g_csr[r * E_];
        const int colOff = r * 128 + j4;
        for (int i = beg; i < end; ++i) {
            int s = srcs[i];
            uint2 u = *(const uint2*)&g_HW[hwBatch + (size_t)s * BN3 + colOff];
            float2 f0 = __half22float2(*(__half2*)&u.x);
            float2 f1 = __half22float2(*(__half2*)&u.y);
            acc.x += f0.x; acc.y += f0.y; acc.z += f1.x; acc.w += f1.y;
        }
    }
    acc.x = fmaxf(acc.x, 0.f);
    acc.y = fmaxf(acc.y, 0.f);
    acc.z = fmaxf(acc.z, 0.f);
    acc.w = fmaxf(acc.w, 0.f);

    size_t hIdx = ((size_t)b * N_ + n) * 128 + j4;
    float4 h = *(const float4*)&H[hIdx];
    float x0 = h.x + acc.x, x1 = h.y + acc.y, x2 = h.z + acc.z, x3 = h.w + acc.w;

    float s = x0 + x1 + x2 + x3;
    float s2 = x0 * x0 + x1 * x1 + x2 * x2 + x3 * x3;
#pragma unroll
    for (int o = 16; o > 0; o >>= 1) {
        s += __shfl_xor_sync(0xffffffffu, s, o);
        s2 += __shfl_xor_sync(0xffffffffu, s2, o);
    }
    float mu = s * (1.f / 128.f);
    float var = s2 * (1.f / 128.f) - mu * mu;
    float inv = rsqrtf(var + 1e-5f);

    float4 gm = *(const float4*)&gamma[j4];
    float4 bb = *(const float4*)&beta[j4];
    float4 out;
    out.x = (x0 - mu) * inv * gm.x + bb.x;
    out.y = (x1 - mu) * inv * gm.y + bb.y;
    out.z = (x2 - mu) * inv * gm.z + bb.z;
    out.w = (x3 - mu) * inv * gm.w + bb.w;
    *(float4*)&H[hIdx] = out;

    if (emitSplit) {
        __nv_bfloat162 h01, h23, m01, m23;
        h01.x = __float2bfloat16_rn(out.x);
        h01.y = __float2bfloat16_rn(out.y);
        h23.x = __float2bfloat16_rn(out.z);
        h23.y = __float2bfloat16_rn(out.w);
        m01.x = __float2bfloat16_rn(out.x - __bfloat162float(h01.x));
        m01.y = __float2bfloat16_rn(out.y - __bfloat162float(h01.y));
        m23.x = __float2bfloat16_rn(out.z - __bfloat162float(h23.x));
        m23.y = __float2bfloat16_rn(out.w - __bfloat162float(h23.y));
        uint2 hv, mv;
        hv.x = *(uint32_t*)&h01; hv.y = *(uint32_t*)&h23;
        mv.x = *(uint32_t*)&m01; mv.y = *(uint32_t*)&m23;
        *(uint2*)&g_Ahi[hIdx] = hv;
        *(uint2*)&g_Amid[hIdx] = mv;
    }
}

// ==================== launch ====================
extern "C" void kernel_launch(void* const* d_in, const int* in_sizes, int n_in,
                              void* d_out, int out_size) {
    const float* node_feat = (const float*)d_in[0];
    const float* in_W      = (const float*)d_in[1];
    const float* in_b      = (const float*)d_in[2];
    const float* node_W    = (const float*)d_in[3];
    const float* node_b    = (const float*)d_in[4];
    const float* edge_W    = (const float*)d_in[5];
    const float* edge_b    = (const float*)d_in[6];
    const float* ln_g      = (const float*)d_in[7];
    const float* ln_b      = (const float*)d_in[8];
    const float* ea0       = (const float*)d_in[9];
    const float* ea1       = (const float*)d_in[10];
    const int*   e0        = (const int*)d_in[11];
    const int*   e1        = (const int*)d_in[12];
    const int*   e2        = (const int*)d_in[13];
    float* H = (float*)d_out;

    __half* hw16 = nullptr;
    cudaGetSymbolAddress((void**)&hw16, g_HW);

    cudaFuncSetAttribute(k_gemm_t<2, false, true>,
                         cudaFuncAttributeMaxDynamicSharedMemorySize, GEMM_SMEM_BYTES);
    cudaFuncSetAttribute(k_gemm_t<4, true, false>,
                         cudaFuncAttributeMaxDynamicSharedMemorySize, GEMM_SMEM_BYTES);

    // index structures + weight pre-split + both layers' edge aggregates
    k_zero<<<(3 * N_ + 255) / 256, 256>>>();
    k_count<<<(3 * E_ + 255) / 256, 256>>>(e0, e1, e2);
    k_scan<<<3, 1024>>>();
    k_fill<<<(3 * E_ + 255) / 256, 256>>>(e0, e1, e2);
    k_gatherS<<<dim3((N_ + 7) / 8, 2), 128>>>(ea0, ea1);
    k_prepW<<<7, 256>>>(in_W, node_W);
    k_eagg<<<dim3(N_, 2), 128>>>(edge_W, edge_b);

    // input projection: H = node_feat @ in_W + in_b; epilogue emits bf16 split of H
    k_prepA<<<(B_ * N_ * DN_ / 4 + 255) / 256, 256>>>(node_feat, 6, B_ * N_ * DN_ / 4);
    k_gemm_t<2, false, true><<<dim3(625, 1), 256, GEMM_SMEM_BYTES>>>(
        0, in_b, 0, H, nullptr, DM_);

    for (int l = 0; l < L_; ++l) {
        // g_HW[:, r] = H @ node_W[l,r] + node_b[l,r]  (fp16 out)
        k_gemm_t<4, true, false><<<dim3(625, 3), 256, GEMM_SMEM_BYTES>>>(
            1 + l * 3, node_b + (size_t)l * 3 * DM_, DM_, nullptr, hw16, BN3);
        k_agg_ln<<<(B_ * N_ * 32 + 255) / 256, 256>>>(H, ln_g + l * DM_, ln_b + l * DM_,
                                                      l, (l == 0) ? 1 : 0);
    }
}

// round 14
// speedup vs baseline: 1.7414x; 1.0887x over previous
#include <cuda_runtime.h>
#include <cuda_bf16.h>
#include <cuda_fp16.h>
#include <cstdint>

// Problem constants (fixed shapes per setup_inputs)
#define B_  4
#define N_  20000
#define DN_ 64
#define DM_ 128
#define E_  160000
#define L_  2
#define BN3 384   // 3 * DM

// ---------------- device scratch (no allocations allowed) ----------------
__device__ __half g_HW[(size_t)B_ * N_ * BN3];  // per-relation transformed nodes (fp16)
__device__ float g_eagg[(size_t)L_ * N_ * DM_]; // per-node edge-term aggregate, both layers
__device__ float g_S[2 * N_ * 16];              // per-node sum of edge attrs per relation
__device__ int   g_deg[3 * N_];
__device__ int   g_off[3 * N_];
__device__ int   g_cur[3 * N_];
__device__ int   g_csr[3 * E_];                 // src node ids grouped by dst
__device__ int   g_csre[3 * E_];                // edge ids grouped by dst
// pre-split, pre-transposed weights: [mat 0..6][hi/mid][n 0..127][k 0..127] bf16
__device__ __nv_bfloat16 g_Wsplit[(size_t)7 * 2 * 128 * 128];
// pre-split activations (A operand), [row 0..79999][k 0..127]
__device__ __nv_bfloat16 g_Ahi[(size_t)B_ * N_ * 128];
__device__ __nv_bfloat16 g_Amid[(size_t)B_ * N_ * 128];

// ==================== CSR build ====================
__global__ void k_zero() {
    int i = blockIdx.x * blockDim.x + threadIdx.x;
    if (i < 3 * N_) g_deg[i] = 0;
}

__global__ void k_count(const int* __restrict__ e0, const int* __restrict__ e1,
                        const int* __restrict__ e2) {
    int t = blockIdx.x * blockDim.x + threadIdx.x;
    if (t >= 3 * E_) return;
    int r = t / E_, e = t - r * E_;
    const int* ei = (r == 0) ? e0 : (r == 1) ? e1 : e2;
    int dst = ei[E_ + e];
    atomicAdd(&g_deg[r * N_ + dst], 1);
}

__global__ void k_scan() {
    __shared__ int sh[1024];
    int r = blockIdx.x;
    int t = threadIdx.x;
    const int CH = 20;
    int base = t * CH;
    int part = 0;
    for (int i = 0; i < CH; ++i) {
        int idx = base + i;
        if (idx < N_) part += g_deg[r * N_ + idx];
    }
    sh[t] = part;
    __syncthreads();
    for (int o = 1; o < 1024; o <<= 1) {
        int v = (t >= o) ? sh[t - o] : 0;
        __syncthreads();
        sh[t] += v;
        __syncthreads();
    }
    int run = (t > 0) ? sh[t - 1] : 0;
    for (int i = 0; i < CH; ++i) {
        int idx = base + i;
        if (idx < N_) {
            g_off[r * N_ + idx] = run;
            g_cur[r * N_ + idx] = run;
            run += g_deg[r * N_ + idx];
        }
    }
}

__global__ void k_fill(const int* __restrict__ e0, const int* __restrict__ e1,
                       const int* __restrict__ e2) {
    int t = blockIdx.x * blockDim.x + threadIdx.x;
    if (t >= 3 * E_) return;
    int r = t / E_, e = t - r * E_;
    const int* ei = (r == 0) ? e0 : (r == 1) ? e1 : e2;
    int src = ei[e];
    int dst = ei[E_ + e];
    int pos = atomicAdd(&g_cur[r * N_ + dst], 1);
    g_csr[r * E_ + pos] = src;
    g_csre[r * E_ + pos] = e;
}

// S_r[n,k] = sum over in-edges of ea_r[e,k]  (gather, deterministic)
__global__ void k_gatherS(const float* __restrict__ ea0, const float* __restrict__ ea1) {
    int n = blockIdx.x * 8 + (threadIdx.x >> 4);
    int k = threadIdx.x & 15;
    int r = blockIdx.y;
    if (n >= N_) return;
    const float* ea = r ? ea1 : ea0;
    const int* __restrict__ eids = &g_csre[r * E_];
    int beg = g_off[r * N_ + n];
    int end = beg + g_deg[r * N_ + n];
    float s = 0.f;
    for (int i = beg; i < end; ++i)
        s += ea[(size_t)eids[i] * 16 + k];
    g_S[(r * N_ + n) * 16 + k] = s;
}

// ==================== weight pre-split (transpose + bf16 hi/mid) ====================
__global__ void k_prepW(const float* __restrict__ in_W, const float* __restrict__ node_W) {
    int m = blockIdx.x;   // 0..6
    const float* src = (m == 0) ? in_W : node_W + (size_t)(m - 1) * 128 * 128;
    int K = (m == 0) ? 64 : 128;
    __nv_bfloat16* hi = g_Wsplit + (size_t)m * 2 * 128 * 128;
    __nv_bfloat16* mid = hi + 128 * 128;
    for (int i = threadIdx.x; i < K * 128; i += blockDim.x) {
        int k = i >> 7, n = i & 127;
        float x = src[i];
        __nv_bfloat16 h = __float2bfloat16_rn(x);
        __nv_bfloat16 md = __float2bfloat16_rn(x - __bfloat162float(h));
        hi[n * 128 + k] = h;
        mid[n * 128 + k] = md;
    }
}

// ==================== activation pre-split (node_feat only, K=64) ====================
__global__ __launch_bounds__(256) void k_prepA(const float* __restrict__ A, int kshift, int total4) {
    int i = blockIdx.x * blockDim.x + threadIdx.x;
    if (i >= total4) return;
    int c4 = i << 2;
    int r = c4 >> kshift;
    int c = c4 & ((1 << kshift) - 1);
    float4 v = *(const float4*)&A[c4];
    __nv_bfloat162 h01, h23, m01, m23;
    h01.x = __float2bfloat16_rn(v.x);
    h01.y = __float2bfloat16_rn(v.y);
    h23.x = __float2bfloat16_rn(v.z);
    h23.y = __float2bfloat16_rn(v.w);
    m01.x = __float2bfloat16_rn(v.x - __bfloat162float(h01.x));
    m01.y = __float2bfloat16_rn(v.y - __bfloat162float(h01.y));
    m23.x = __float2bfloat16_rn(v.z - __bfloat162float(h23.x));
    m23.y = __float2bfloat16_rn(v.w - __bfloat162float(h23.y));
    size_t o = (size_t)r * 128 + c;
    uint2 hv, mv;
    hv.x = *(uint32_t*)&h01; hv.y = *(uint32_t*)&h23;
    mv.x = *(uint32_t*)&m01; mv.y = *(uint32_t*)&m23;
    *(uint2*)&g_Ahi[o] = hv;
    *(uint2*)&g_Amid[o] = mv;
}

// ==================== HMMA GEMM (cp.async double-buffered, fat warp tiles) ====================
// CTA tile 128x128, 128 thr = 4 warps (2M x 2N), warp tile 64x64 -> 48 FLOP/smem-byte
// (MMA-bound). BK=32, 2 stages, 80 KB smem, __launch_bounds__(128,2) -> 2 CTA/SM.
#define SROW 40
#define ARR_ELEMS (128 * SROW)
#define GEMM_SMEM_BYTES (2 * 4 * ARR_ELEMS * 2)   // 81920

__device__ __forceinline__ uint32_t smem_u32(const void* p) {
    uint32_t a;
    asm("{ .reg .u64 t; cvta.to.shared.u64 t, %1; cvt.u32.u64 %0, t; }" : "=r"(a) : "l"(p));
    return a;
}
__device__ __forceinline__ void cp16(uint32_t dst, const void* src) {
    asm volatile("cp.async.ca.shared.global [%0], [%1], 16;" :: "r"(dst), "l"(src));
}
#define CP_COMMIT() asm volatile("cp.async.commit_group;" ::: "memory")

__device__ __forceinline__ void mma16816(float* c, const uint32_t* a, const uint32_t* b) {
    asm volatile(
        "mma.sync.aligned.m16n8k16.row.col.f32.bf16.bf16.f32 "
        "{%0,%1,%2,%3}, {%4,%5,%6,%7}, {%8,%9}, {%0,%1,%2,%3};"
        : "+f"(c[0]), "+f"(c[1]), "+f"(c[2]), "+f"(c[3])
        : "r"(a[0]), "r"(a[1]), "r"(a[2]), "r"(a[3]), "r"(b[0]), "r"(b[1]));
}

template<int NSTAGES, bool OUT16, bool EMIT>
__global__ __launch_bounds__(128, 2)
void k_gemm_t(int matBase, const float* __restrict__ biasBase, int strideBias,
              float* __restrict__ outF32, __half* __restrict__ outF16, int ldC) {
    extern __shared__ __nv_bfloat16 smem[];
    const int tid = threadIdx.x;
    const int wid = tid >> 5;
    const int lane = tid & 31;
    const int g = lane >> 2;
    const int t = lane & 3;
    const int wm = wid & 1;       // warp row (2): rows wm*64..+63
    const int wn = wid >> 1;      // warp col (2): cols wn*64..+63
    const int row0 = blockIdx.x * 128;
    const int mat = matBase + blockIdx.y;
    const float* bias = biasBase + (size_t)blockIdx.y * strideBias;
    const int colBase = blockIdx.y * 128;
    const __nv_bfloat16* Whi = g_Wsplit + (size_t)mat * 2 * 128 * 128;
    const __nv_bfloat16* Wmid = Whi + 128 * 128;
    const uint32_t sb = smem_u32(smem);

    float acc[4][8][4];
#pragma unroll
    for (int i = 0; i < 4; ++i)
#pragma unroll
        for (int j = 0; j < 8; ++j)
#pragma unroll
            for (int q = 0; q < 4; ++q) acc[i][j][q] = 0.f;

    auto issueStage = [&](int buf, int kc) {
#pragma unroll
        for (int tt = 0; tt < 16; ++tt) {
            int f = tid + tt * 128;           // 2048 chunks per stage
            int arr = f >> 9;
            int gg = f & 511;
            int row = gg >> 2;
            int u = (gg & 3) * 8;
            const __nv_bfloat16* src;
            if (arr == 0)      src = &g_Ahi[(size_t)(row0 + row) * 128 + kc + u];
            else if (arr == 1) src = &g_Amid[(size_t)(row0 + row) * 128 + kc + u];
            else if (arr == 2) src = &Whi[(size_t)row * 128 + kc + u];
            else               src = &Wmid[(size_t)row * 128 + kc + u];
            uint32_t dst = sb + ((buf * 4 + arr) * ARR_ELEMS + row * SROW + u) * 2;
            cp16(dst, src);
        }
        CP_COMMIT();
    };

    issueStage(0, 0);

#pragma unroll
    for (int st = 0; st < NSTAGES; ++st) {
        const int buf = st & 1;
        if (st + 1 < NSTAGES) {
            issueStage(buf ^ 1, (st + 1) << 5);
            asm volatile("cp.async.wait_group 1;" ::: "memory");
        } else {
            asm volatile("cp.async.wait_group 0;" ::: "memory");
        }
        __syncthreads();

        const __nv_bfloat16* sAhi  = smem + (buf * 4 + 0) * ARR_ELEMS;
        const __nv_bfloat16* sAmid = smem + (buf * 4 + 1) * ARR_ELEMS;
        const __nv_bfloat16* sBhi  = smem + (buf * 4 + 2) * ARR_ELEMS;
        const __nv_bfloat16* sBmid = smem + (buf * 4 + 3) * ARR_ELEMS;

#pragma unroll
        for (int kk = 0; kk < 2; ++kk) {
            const int k0 = kk << 4;
            uint32_t bh[8][2], bm[8][2];
#pragma unroll
            for (int j = 0; j < 8; ++j) {
                int n_idx = wn * 64 + j * 8 + g;
                int o0 = n_idx * SROW + k0 + t * 2;
                bh[j][0] = *(const uint32_t*)&sBhi[o0];
                bh[j][1] = *(const uint32_t*)&sBhi[o0 + 8];
                bm[j][0] = *(const uint32_t*)&sBmid[o0];
                bm[j][1] = *(const uint32_t*)&sBmid[o0 + 8];
            }
#pragma unroll
            for (int i = 0; i < 4; ++i) {
                int m_idx = wm * 64 + i * 16 + g;
                int o0 = m_idx * SROW + k0 + t * 2;
                int o8 = (m_idx + 8) * SROW + k0 + t * 2;
                uint32_t ah[4], am[4];
                ah[0] = *(const uint32_t*)&sAhi[o0];
                ah[1] = *(const uint32_t*)&sAhi[o8];
                ah[2] = *(const uint32_t*)&sAhi[o0 + 8];
                ah[3] = *(const uint32_t*)&sAhi[o8 + 8];
                am[0] = *(const uint32_t*)&sAmid[o0];
                am[1] = *(const uint32_t*)&sAmid[o8];
                am[2] = *(const uint32_t*)&sAmid[o0 + 8];
                am[3] = *(const uint32_t*)&sAmid[o8 + 8];
#pragma unroll
                for (int j = 0; j < 8; ++j) {
                    mma16816(acc[i][j], ah, bh[j]);   // hi*hi
                    mma16816(acc[i][j], ah, bm[j]);   // hi*mid
                    mma16816(acc[i][j], am, bh[j]);   // mid*hi
                }
            }
        }
        __syncthreads();
    }

    // ---- epilogue (compile-time specialized) ----
#pragma unroll
    for (int i = 0; i < 4; ++i) {
#pragma unroll
        for (int j = 0; j < 8; ++j) {
            int col = wn * 64 + j * 8 + t * 2;
            int row = row0 + wm * 64 + i * 16 + g;
            float b0 = bias[col], b1 = bias[col + 1];
            float v00 = acc[i][j][0] + b0, v01 = acc[i][j][1] + b1;
            float v10 = acc[i][j][2] + b0, v11 = acc[i][j][3] + b1;
            if (!OUT16) {
                *(float2*)&outF32[(size_t)row * ldC + colBase + col] = make_float2(v00, v01);
                *(float2*)&outF32[(size_t)(row + 8) * ldC + colBase + col] = make_float2(v10, v11);
            } else {
                __half2 h0 = __float22half2_rn(make_float2(v00, v01));
                __half2 h1 = __float22half2_rn(make_float2(v10, v11));
                *(__half2*)&outF16[(size_t)row * ldC + colBase + col] = h0;
                *(__half2*)&outF16[(size_t)(row + 8) * ldC + colBase + col] = h1;
            }
            if (EMIT) {
                __nv_bfloat162 h0, m0, h1, m1;
                h0.x = __float2bfloat16_rn(v00); h0.y = __float2bfloat16_rn(v01);
                m0.x = __float2bfloat16_rn(v00 - __bfloat162float(h0.x));
                m0.y = __float2bfloat16_rn(v01 - __bfloat162float(h0.y));
                h1.x = __float2bfloat16_rn(v10); h1.y = __float2bfloat16_rn(v11);
                m1.x = __float2bfloat16_rn(v10 - __bfloat162float(h1.x));
                m1.y = __float2bfloat16_rn(v11 - __bfloat162float(h1.y));
                *(__nv_bfloat162*)&g_Ahi[(size_t)row * 128 + colBase + col] = h0;
                *(__nv_bfloat162*)&g_Amid[(size_t)row * 128 + colBase + col] = m0;
                *(__nv_bfloat162*)&g_Ahi[(size_t)(row + 8) * 128 + colBase + col] = h1;
                *(__nv_bfloat162*)&g_Amid[(size_t)(row + 8) * 128 + colBase + col] = m1;
            }
        }
    }
}

// ==================== edge-term aggregate, both layers precomputed ====================
__global__ void k_eagg(const float* __restrict__ edge_W, const float* __restrict__ edge_b) {
    int n = blockIdx.x;
    int l = blockIdx.y;
    int j = threadIdx.x;   // 128
    __shared__ float s0[16], s1[16];
    if (j < 16) s0[j] = g_S[(0 * N_ + n) * 16 + j];
    else if (j < 32) s1[j - 16] = g_S[(1 * N_ + n) * 16 + (j - 16)];
    __syncthreads();

    const float* W0 = edge_W + (size_t)(l * 2 + 0) * 16 * 128;
    const float* W1 = edge_W + (size_t)(l * 2 + 1) * 16 * 128;
    float d0 = (float)g_deg[0 * N_ + n];
    float d1 = (float)g_deg[1 * N_ + n];
    float acc = d0 * edge_b[(l * 2 + 0) * 128 + j] + d1 * edge_b[(l * 2 + 1) * 128 + j];
#pragma unroll
    for (int k = 0; k < 16; ++k) acc = fmaf(s0[k], W0[k * 128 + j], acc);
#pragma unroll
    for (int k = 0; k < 16; ++k) acc = fmaf(s1[k], W1[k * 128 + j], acc);
    g_eagg[((size_t)l * N_ + n) * 128 + j] = acc;
}

// ==================== fused gather-aggregate + relu + residual + LayerNorm ====================
__global__ __launch_bounds__(256) void k_agg_ln(float* __restrict__ H,
                                                const float* __restrict__ gamma,
                                                const float* __restrict__ beta,
                                                int l, int emitSplit) {
    int warp = (blockIdx.x * blockDim.x + threadIdx.x) >> 5;
    int lane = threadIdx.x & 31;
    if (warp >= B_ * N_) return;
    int b = warp / N_;
    int n = warp - b * N_;
    int j4 = lane * 4;

    float4 acc = *(const float4*)&g_eagg[((size_t)l * N_ + n) * 128 + j4];
    const size_t hwBatch = (size_t)b * N_ * BN3;

#pragma unroll
    for (int r = 0; r < 3; ++r) {
        int beg = g_off[r * N_ + n];
        int end = beg + g_deg[r * N_ + n];
        const int* __restrict__ srcs = &g_csr[r * E_];
        const int colOff = r * 128 + j4;
        int i = beg;
        // 2-way unroll: two independent idx->data chains in flight
        for (; i + 2 <= end; i += 2) {
            int sA = srcs[i];
            int sB = srcs[i + 1];
            uint2 uA = *(const uint2*)&g_HW[hwBatch + (size_t)sA * BN3 + colOff];
            uint2 uB = *(const uint2*)&g_HW[hwBatch + (size_t)sB * BN3 + colOff];
            float2 a0 = __half22float2(*(__half2*)&uA.x);
            float2 a1 = __half22float2(*(__half2*)&uA.y);
            float2 b0 = __half22float2(*(__half2*)&uB.x);
            float2 b1 = __half22float2(*(__half2*)&uB.y);
            acc.x += a0.x + b0.x; acc.y += a0.y + b0.y;
            acc.z += a1.x + b1.x; acc.w += a1.y + b1.y;
        }
        if (i < end) {
            int s = srcs[i];
            uint2 u = *(const uint2*)&g_HW[hwBatch + (size_t)s * BN3 + colOff];
            float2 f0 = __half22float2(*(__half2*)&u.x);
            float2 f1 = __half22float2(*(__half2*)&u.y);
            acc.x += f0.x; acc.y += f0.y; acc.z += f1.x; acc.w += f1.y;
        }
    }
    acc.x = fmaxf(acc.x, 0.f);
    acc.y = fmaxf(acc.y, 0.f);
    acc.z = fmaxf(acc.z, 0.f);
    acc.w = fmaxf(acc.w, 0.f);

    size_t hIdx = ((size_t)b * N_ + n) * 128 + j4;
    float4 h = *(const float4*)&H[hIdx];
    float x0 = h.x + acc.x, x1 = h.y + acc.y, x2 = h.z + acc.z, x3 = h.w + acc.w;

    float s = x0 + x1 + x2 + x3;
    float s2 = x0 * x0 + x1 * x1 + x2 * x2 + x3 * x3;
#pragma unroll
    for (int o = 16; o > 0; o >>= 1) {
        s += __shfl_xor_sync(0xffffffffu, s, o);
        s2 += __shfl_xor_sync(0xffffffffu, s2, o);
    }
    float mu = s * (1.f / 128.f);
    float var = s2 * (1.f / 128.f) - mu * mu;
    float inv = rsqrtf(var + 1e-5f);

    float4 gm = *(const float4*)&gamma[j4];
    float4 bb = *(const float4*)&beta[j4];
    float4 out;
    out.x = (x0 - mu) * inv * gm.x + bb.x;
    out.y = (x1 - mu) * inv * gm.y + bb.y;
    out.z = (x2 - mu) * inv * gm.z + bb.z;
    out.w = (x3 - mu) * inv * gm.w + bb.w;
    *(float4*)&H[hIdx] = out;

    if (emitSplit) {
        __nv_bfloat162 h01, h23, m01, m23;
        h01.x = __float2bfloat16_rn(out.x);
        h01.y = __float2bfloat16_rn(out.y);
        h23.x = __float2bfloat16_rn(out.z);
        h23.y = __float2bfloat16_rn(out.w);
        m01.x = __float2bfloat16_rn(out.x - __bfloat162float(h01.x));
        m01.y = __float2bfloat16_rn(out.y - __bfloat162float(h01.y));
        m23.x = __float2bfloat16_rn(out.z - __bfloat162float(h23.x));
        m23.y = __float2bfloat16_rn(out.w - __bfloat162float(h23.y));
        uint2 hv, mv;
        hv.x = *(uint32_t*)&h01; hv.y = *(uint32_t*)&h23;
        mv.x = *(uint32_t*)&m01; mv.y = *(uint32_t*)&m23;
        *(uint2*)&g_Ahi[hIdx] = hv;
        *(uint2*)&g_Amid[hIdx] = mv;
    }
}

// ==================== launch ====================
extern "C" void kernel_launch(void* const* d_in, const int* in_sizes, int n_in,
                              void* d_out, int out_size) {
    const float* node_feat = (const float*)d_in[0];
    const float* in_W      = (const float*)d_in[1];
    const float* in_b      = (const float*)d_in[2];
    const float* node_W    = (const float*)d_in[3];
    const float* node_b    = (const float*)d_in[4];
    const float* edge_W    = (const float*)d_in[5];
    const float* edge_b    = (const float*)d_in[6];
    const float* ln_g      = (const float*)d_in[7];
    const float* ln_b      = (const float*)d_in[8];
    const float* ea0       = (const float*)d_in[9];
    const float* ea1       = (const float*)d_in[10];
    const int*   e0        = (const int*)d_in[11];
    const int*   e1        = (const int*)d_in[12];
    const int*   e2        = (const int*)d_in[13];
    float* H = (float*)d_out;

    __half* hw16 = nullptr;
    cudaGetSymbolAddress((void**)&hw16, g_HW);

    cudaFuncSetAttribute(k_gemm_t<2, false, true>,
                         cudaFuncAttributeMaxDynamicSharedMemorySize, GEMM_SMEM_BYTES);
    cudaFuncSetAttribute(k_gemm_t<4, true, false>,
                         cudaFuncAttributeMaxDynamicSharedMemorySize, GEMM_SMEM_BYTES);

    // index structures + weight pre-split + both layers' edge aggregates
    k_zero<<<(3 * N_ + 255) / 256, 256>>>();
    k_count<<<(3 * E_ + 255) / 256, 256>>>(e0, e1, e2);
    k_scan<<<3, 1024>>>();
    k_fill<<<(3 * E_ + 255) / 256, 256>>>(e0, e1, e2);
    k_gatherS<<<dim3((N_ + 7) / 8, 2), 128>>>(ea0, ea1);
    k_prepW<<<7, 256>>>(in_W, node_W);
    k_eagg<<<dim3(N_, 2), 128>>>(edge_W, edge_b);

    // input projection: H = node_feat @ in_W + in_b; epilogue emits bf16 split of H
    k_prepA<<<(B_ * N_ * DN_ / 4 + 255) / 256, 256>>>(node_feat, 6, B_ * N_ * DN_ / 4);
    k_gemm_t<2, false, true><<<dim3(625, 1), 128, GEMM_SMEM_BYTES>>>(
        0, in_b, 0, H, nullptr, DM_);

    for (int l = 0; l < L_; ++l) {
        // g_HW[:, r] = H @ node_W[l,r] + node_b[l,r]  (fp16 out)
        k_gemm_t<4, true, false><<<dim3(625, 3), 128, GEMM_SMEM_BYTES>>>(
            1 + l * 3, node_b + (size_t)l * 3 * DM_, DM_, nullptr, hw16, BN3);
        k_agg_ln<<<(B_ * N_ * 32 + 255) / 256, 256>>>(H, ln_g + l * DM_, ln_b + l * DM_,
                                                      l, (l == 0) ? 1 : 0);
    }
}